// round 13
// baseline (speedup 1.0000x reference)
#include <cuda_runtime.h>
#include <cuda_fp16.h>
#include <cstdint>

// ---------------------------------------------------------------------------
// UniformSpline log-prob (inverse rational-quadratic spline logdet)
//   x: (2097152, 8) f32   uw,uh: (8,128) f32   ud: (8,127) f32
//   out = log(0.5) - logabsdet(x), identity tails -> log(0.5)
//
// Channel-parity split: even CTAs handle channels 0-3 (even float4 quads),
// odd CTAs channels 4-7 (odd quads). 2 CTAs x 768 threads per SM = 48 warps.
// LUT cell {e0, h, delta, half2(d0,t)} -> ONE LDS.128 per element; the rare
// knot-crossing reload is a hand-predicated @p ld.shared (ptxas would emit a
// BSSY/BSYNC divergence envelope for the equivalent C++ if{}).
// ---------------------------------------------------------------------------

#define CPC   4        // channels per CTA
#define NBINS 128
#define NLUT  1024

#define SC_OFF   0                                    // float4 sC[4][NLUT+2]
#define SC_BYTES (CPC * (NLUT + 2) * 16)
#define ST_OFF   (SC_OFF + SC_BYTES)                  // float4 sT[4][128]
#define ST_BYTES (CPC * NBINS * 16)
#define SE_OFF   (ST_OFF + ST_BYTES)                  // float sE[4][129]
#define SE_BYTES (CPC * (NBINS + 1) * 4)
#define SMEM_TOTAL (SE_OFF + SE_BYTES)

#define RCPA(o,a)   asm("rcp.approx.f32 %0, %1;"  : "=f"(o) : "f"(a))
#define SQRTA(o,a)  asm("sqrt.approx.f32 %0, %1;" : "=f"(o) : "f"(a))
#define LG2A(o,a)   asm("lg2.approx.f32 %0, %1;"  : "=f"(o) : "f"(a))

__device__ __forceinline__ float softplus_md(float v) {
    return 1e-3f + log1pf(expf(v));      // MIN_DERIVATIVE + softplus
}

// Per-warp (one channel) softmax(10u)+min-size cumsum -> knots in [-1,1].
__device__ __forceinline__ void edges4(const float* __restrict__ src_row,
                                       int l, float e[5]) {
    float u[4], ex[4];
#pragma unroll
    for (int k = 0; k < 4; k++) u[k] = 10.0f * src_row[l * 4 + k];
    float m = fmaxf(fmaxf(u[0], u[1]), fmaxf(u[2], u[3]));
#pragma unroll
    for (int off = 16; off; off >>= 1) m = fmaxf(m, __shfl_xor_sync(0xffffffffu, m, off));
#pragma unroll
    for (int k = 0; k < 4; k++) ex[k] = expf(u[k] - m);
    float ls = ex[0] + ex[1] + ex[2] + ex[3];

    float sc = ls;
#pragma unroll
    for (int off = 1; off < 32; off <<= 1) {
        float v = __shfl_up_sync(0xffffffffu, sc, off);
        if (l >= off) sc += v;
    }
    const float invS = 1.0f / __shfl_sync(0xffffffffu, sc, 31);
    float ce = sc - ls;

    e[0] = (l == 0) ? -1.0f
                    : 2.0f * (1e-3f * (float)(4 * l) + 0.872f * ce * invS) - 1.0f;
#pragma unroll
    for (int k = 0; k < 4; k++) {
        ce += ex[k];
        int j = l * 4 + k + 1;
        e[k + 1] = (j == NBINS) ? 1.0f
                                : 2.0f * (1e-3f * (float)j + 0.872f * ce * invS) - 1.0f;
    }
}

// One element, local channel J (compile-time).
template<int J>
__device__ __forceinline__ float spline_eval(float x, const float4 (*sC)[NLUT + 2]) {
    const float LOG_HALF = -0.6931471805599453f;
    const float LN2      =  0.6931471805599453f;

    const float xc = fminf(fmaxf(x, -1.0f), 1.0f);
    int q = (int)fmaf(xc, 512.0f, 512.0f);    // in [0, 1024]; 1024 -> sentinel cell
    const float4* cp = &sC[J][q];
    float4 cl = *cp;                           // {e0, h, delta, half2(d0,t)}
    float dy = xc - cl.x;

    // Predicated crossing reload (no BSSY/BSYNC): if dy > h, the element is in
    // the next bin, whose params live in cell q+1 (<=1 knot per cell).
    unsigned a1 = (unsigned)__cvta_generic_to_shared(cp + 1);
    asm("{\n\t"
        ".reg .pred p;\n\t"
        "setp.gt.f32 p, %4, %1;\n\t"
        "@p ld.shared.v4.f32 {%0, %1, %2, %3}, [%5];\n\t"
        "}"
        : "+f"(cl.x), "+f"(cl.y), "+f"(cl.z), "+f"(cl.w)
        : "f"(dy), "r"(a1));
    dy = xc - cl.x;

    unsigned hu = __float_as_uint(cl.w);
    float2 dt = __half22float2(*reinterpret_cast<const __half2*>(&hu));
    const float h = cl.y, dl = cl.z, d0 = dt.x, t = dt.y;

    float dmd  = dl - d0;
    float dyt  = dy * t;
    float aa   = fmaf(h, dmd, dyt);
    float bb   = fmaf(h, d0, -dyt);
    float g    = dl * dy;                     // -c
    float disc = fmaxf(fmaf(bb, bb, 4.0f * (aa * g)), 0.0f);
    float s;   SQRTA(s, disc);
    float rw;  RCPA(rw, bb + s);
    float root = (g + g) * rw;
    float th   = fmaf(-root, root, root);     // root*(1-root)
    float den  = fmaf(t, th, dl);
    float pp   = fmaf(fmaf(t, root, dmd + dmd), root, d0);
    float num  = (dl * dl) * pp;
    float lgn;  LG2A(lgn, num);
    float lgd;  LG2A(lgd, den);
    float m2   = fmaf(-2.0f, lgd, lgn);       // lg2(num/den^2)
    float inside = fmaf(-LN2, m2, LOG_HALF);

    return (fabsf(x) <= 1.0f) ? inside : LOG_HALF;
}

__global__ void __launch_bounds__(768, 2)
spline_fused_kernel(const float4* __restrict__ x4, float4* __restrict__ o4, int nquads,
                    const float* __restrict__ uw, const float* __restrict__ uh,
                    const float* __restrict__ ud)
{
    extern __shared__ unsigned char smem_raw[];
    float4 (*sC)[NLUT + 2]  = (float4 (*)[NLUT + 2])(smem_raw + SC_OFF);
    float4 (*sT)[NBINS]     = (float4 (*)[NBINS])   (smem_raw + ST_OFF);
    float  (*sE)[NBINS + 1] = (float (*)[NBINS + 1])(smem_raw + SE_OFF);

    const int tid = threadIdx.x;
    const int l   = tid & 31;
    const int par = blockIdx.x & 1;          // 0 -> channels 0-3, 1 -> channels 4-7

    // ---- table build: warps 0..3 -> local channel = warp id ----
    if (tid < 32 * CPC) {
        const int cl_ = tid >> 5;            // local channel
        const int cg  = par * CPC + cl_;     // global channel
        const float DI = logf(expf(1.0f - 1e-3f) - 1.0f);
        const float DT = softplus_md(DI);    // tail derivative == 1.0

        float ew[5], eh[5];
        edges4(uw + cg * NBINS, l, ew);
        edges4(uh + cg * NBINS, l, eh);

        float dd[5];
#pragma unroll
        for (int m2 = 0; m2 < 5; m2++) {
            int k = 4 * l + m2;
            dd[m2] = (k == 0 || k == NBINS) ? DT
                     : softplus_md(ud[cg * (NBINS - 1) + k - 1]);
        }

#pragma unroll
        for (int k = 0; k < 4; k++) sE[cl_][4 * l + k] = eh[k];
        if (l == 31) sE[cl_][NBINS] = eh[4];

#pragma unroll
        for (int k = 0; k < 4; k++) {
            float h  = eh[k + 1] - eh[k];
            float dl = h / (ew[k + 1] - ew[k]);
            sT[cl_][4 * l + k] = make_float4(h, dl, dd[k], dd[k] + dd[k + 1] - 2.0f * dl);
        }
    }
    __syncthreads();

    // ---- LUT: 128 threads per local channel, 8 cells each ----
    if (tid < 128 * CPC) {
        const int c     = tid >> 7;
        const int cell0 = (tid & 127) * 8;
        const float* E  = &sE[c][0];
        float v = (float)cell0 * (1.0f / 512.0f) - 1.0f;
        int lo = 0;
#pragma unroll
        for (int step = 64; step; step >>= 1)
            if (lo + step <= NBINS - 1 && E[lo + step] <= v) lo += step;
        for (int q = 0; q < 8; q++) {
            float vq = (float)(cell0 + q) * (1.0f / 512.0f) - 1.0f;
            while (lo < NBINS - 1 && E[lo + 1] <= vq) lo++;
            float4 tq = sT[c][lo];
            __half2 hp = __floats2half2_rn(tq.z, tq.w);
            unsigned hu = *reinterpret_cast<unsigned*>(&hp);
            sC[c][cell0 + q] = make_float4(E[lo], tq.x, tq.y, __uint_as_float(hu));
        }
        if ((tid & 127) == 127) {             // sentinels: q==1024 load, q+1==1025 guard
            sC[c][NLUT]     = sC[c][NLUT - 1];
            sC[c][NLUT + 1] = sC[c][NLUT - 1];
        }
    }
    __syncthreads();

    // ---- main pass: this CTA's parity of float4 quads (its 4 channels) ----
    const int half_blocks = gridDim.x >> 1;
    const int stride = half_blocks * blockDim.x;

    for (int qd = (blockIdx.x >> 1) * blockDim.x + tid; qd < nquads; qd += stride) {
        const int i = 2 * qd + par;
        float4 a = x4[i];
        float4 r;
        r.x = spline_eval<0>(a.x, sC);
        r.y = spline_eval<1>(a.y, sC);
        r.z = spline_eval<2>(a.z, sC);
        r.w = spline_eval<3>(a.w, sC);
        o4[i] = r;
    }
}

// ---------------------------------------------------------------------------
extern "C" void kernel_launch(void* const* d_in, const int* in_sizes, int n_in,
                              void* d_out, int out_size)
{
    const float* x  = (const float*)d_in[0];
    const float* uw = (const float*)d_in[1];
    const float* uh = (const float*)d_in[2];
    const float* ud = (const float*)d_in[3];

    cudaFuncSetAttribute(spline_fused_kernel,
                         cudaFuncAttributeMaxDynamicSharedMemorySize, SMEM_TOTAL);

    const int nquads = out_size / 8;     // float4 quads per parity
    spline_fused_kernel<<<296, 768, SMEM_TOTAL>>>((const float4*)x, (float4*)d_out,
                                                  nquads, uw, uh, ud);
}